// round 16
// baseline (speedup 1.0000x reference)
#include <cuda_runtime.h>
#include <cuda_bf16.h>
#include <stdint.h>

typedef unsigned long long ull;

#define NB   1024
#define SS   16
#define AA   8
#define NACT 16
#define SD   256
#define EM   256

// ---------------- device scratch ----------------
__device__ float g_sW1[NB*EM];
__device__ float g_v[NB];
// GEMM2 B (W2^T) fragments: [kblk(16)][nblk(32)][lane(32)][reg(2)] u32, split hi/lo
__device__ uint32_t g_Bh[16*32*32*2];
__device__ uint32_t g_Bl[16*32*32*2];
// GEMM1 B (W1x) fragments: [kblk(8)][nblk(32)][lane(32)][reg(2)] u32, split hi/lo
__device__ uint32_t g_B1h[8*32*32*2];
__device__ uint32_t g_B1l[8*32*32*2];

// ---------------- threefry2x32 (JAX exact, key(42)) ----------------
__device__ __forceinline__ uint32_t rotl(uint32_t x, int r){ return (x<<r)|(x>>(32-r)); }
__device__ __forceinline__ void threefry2x32(uint32_t c0, uint32_t c1, uint32_t &o0, uint32_t &o1){
  const uint32_t k0 = 0u, k1v = 42u, k2 = 0u ^ 42u ^ 0x1BD11BDAu;
  uint32_t x0 = c0 + k0;
  uint32_t x1 = c1 + k1v;
#define TF_R(rot) { x0 += x1; x1 = rotl(x1, rot); x1 ^= x0; }
  TF_R(13) TF_R(15) TF_R(26) TF_R(6)
  x0 += k1v; x1 += k2 + 1u;
  TF_R(17) TF_R(29) TF_R(16) TF_R(24)
  x0 += k2;  x1 += k0 + 2u;
  TF_R(13) TF_R(15) TF_R(26) TF_R(6)
  x0 += k0;  x1 += k1v + 3u;
  TF_R(17) TF_R(29) TF_R(16) TF_R(24)
  x0 += k1v; x1 += k2 + 4u;
  TF_R(13) TF_R(15) TF_R(26) TF_R(6)
  x0 += k2;  x1 += k0 + 5u;
#undef TF_R
  o0 = x0; o1 = x1;
}
__device__ __forceinline__ float bits_to_unit(uint32_t bits){
  return __uint_as_float(0x3f800000u | (bits >> 9)) - 1.0f;
}

// ---------------- packed helpers ----------------
__device__ __forceinline__ uint32_t pack_bf16x2(float v0, float v1){
  uint32_t r;
  asm("cvt.rn.bf16x2.f32 %0, %1, %2;" : "=r"(r) : "f"(v1), "f"(v0));
  return r;
}
__device__ __forceinline__ void split2(float v0, float v1, uint32_t &h, uint32_t &l){
  h = pack_bf16x2(v0, v1);
  float h0 = __uint_as_float(h << 16);
  float h1 = __uint_as_float(h & 0xFFFF0000u);
  l = pack_bf16x2(v0 - h0, v1 - h1);
}
__device__ __forceinline__ void split_bf16(float v, uint32_t &h, uint32_t &l){
  __nv_bfloat16 hb = __float2bfloat16(v);
  float lf = v - __bfloat162float(hb);
  __nv_bfloat16 lb = __float2bfloat16(lf);
  h = (uint32_t)__bfloat16_as_ushort(hb);
  l = (uint32_t)__bfloat16_as_ushort(lb);
}

__device__ __forceinline__ void mma16816(float* d, const uint32_t* a, uint32_t b0, uint32_t b1){
  asm volatile("mma.sync.aligned.m16n8k16.row.col.f32.bf16.bf16.f32 "
    "{%0,%1,%2,%3}, {%4,%5,%6,%7}, {%8,%9}, {%0,%1,%2,%3};"
    : "+f"(d[0]),"+f"(d[1]),"+f"(d[2]),"+f"(d[3])
    : "r"(a[0]),"r"(a[1]),"r"(a[2]),"r"(a[3]), "r"(b0),"r"(b1));
}

// ============ K0: W2 -> GEMM2 B fragments ============
__global__ void k0_prepW2(const float* __restrict__ W2){
  int idx = blockIdx.x*256 + threadIdx.x;   // 32768
  int kp = idx >> 8, n = idx & 255;
  int k = kp*2;
  float v0 = W2[k*EM + n];
  float v1 = W2[(k+1)*EM + n];
  uint32_t h0,l0,h1,l1;
  split_bf16(v0,h0,l0); split_bf16(v1,h1,l1);
  uint32_t hi = h0 | (h1<<16);
  uint32_t lo = l0 | (l1<<16);
  int kblk = kp>>3;
  int reg  = (kp>>2)&1;
  int lane = (n&7)*4 + (kp&3);
  int nblk = n>>3;
  int bidx = ((kblk*32+nblk)*32+lane)*2 + reg;
  g_Bh[bidx] = hi;
  g_Bl[bidx] = lo;
}

// ============ K0b: W1x (rows SD..SD+127) -> GEMM1 B fragments ============
__global__ void k0b_prepW1x(const float* __restrict__ W1){
  int idx = blockIdx.x*256 + threadIdx.x;   // 16384
  int kp = idx >> 8, n = idx & 255;
  int k = kp*2;
  float v0 = W1[(SD + k)*EM + n];
  float v1 = W1[(SD + k + 1)*EM + n];
  uint32_t h0,l0,h1,l1;
  split_bf16(v0,h0,l0); split_bf16(v1,h1,l1);
  uint32_t hi = h0 | (h1<<16);
  uint32_t lo = l0 | (l1<<16);
  int kblk = kp>>3;          // 0..7 = agent position a
  int reg  = (kp>>2)&1;
  int lane = (n&7)*4 + (kp&3);
  int nblk = n>>3;
  int bidx = ((kblk*32+nblk)*32+lane)*2 + reg;
  g_B1h[bidx] = hi;
  g_B1l[bidx] = lo;
}

// ============ K1: per-b state terms, 4 b per CTA ============
__global__ void __launch_bounds__(256) k1_state(const float* __restrict__ st,
                         const float* __restrict__ W1,
                         const float* __restrict__ b1, const float* __restrict__ Vw1,
                         const float* __restrict__ Vb1, const float* __restrict__ Vw2,
                         const float* __restrict__ Vb2){
  const int b0 = blockIdx.x * 4;
  const int n  = threadIdx.x;
  __shared__ float s_st[4][SD];
  __shared__ float red[4][EM];
  #pragma unroll
  for(int bi=0;bi<4;bi++) s_st[bi][n] = st[(b0+bi)*SD + n];
  __syncthreads();
  float acc[4], accv[4];
  float bb1 = b1[n], vbb = Vb1[n];
  #pragma unroll
  for(int bi=0;bi<4;bi++){ acc[bi]=bb1; accv[bi]=vbb; }
  #pragma unroll 4
  for(int k=0;k<SD;k++){
    float w  = W1 [k*EM + n];
    float vw = Vw1[k*EM + n];
    #pragma unroll
    for(int bi=0;bi<4;bi++){
      float sv = s_st[bi][k];
      acc[bi]  = fmaf(sv, w,  acc[bi]);
      accv[bi] = fmaf(sv, vw, accv[bi]);
    }
  }
  float vw2 = Vw2[n];
  #pragma unroll
  for(int bi=0;bi<4;bi++){
    g_sW1[(b0+bi)*EM + n] = acc[bi];
    red[bi][n] = fmaxf(accv[bi], 0.f) * vw2;
  }
  __syncthreads();
  int w = n >> 5, l = n & 31;
  if (w < 4){
    float s = 0.f;
    #pragma unroll
    for(int t=0;t<8;t++) s += red[w][l + t*32];
    #pragma unroll
    for(int off=16; off>0; off>>=1) s += __shfl_xor_sync(0xFFFFFFFFu, s, off);
    if (l == 0) g_v[b0 + w] = s + Vb2[0];
  }
}

// ============ Fused: RNG + delta-MMA + prefix-scan emit + GEMM2 + shapley ============
// smem layout (bytes)
#define S_A2H 0                 // 65536: GEMM2 A hi frags [mblk*16+kblk][lane][4]
#define S_A2L 65536             // 65536: GEMM2 A lo frags
#define S_BH  131072            // 16384: GEMM2 B hi dbuf [buf][2048 u32]
#define S_BL  147456            // 16384: GEMM2 B lo dbuf
#define S_D   163840            // 33792: delta chunk [s*8+a][66 floats]
#define S_RQH 197632            // 4096: rq hi pairs [s(16)][a(8)][pr(8)]
#define S_RQL 201728            // 4096
#define S_SW1 205824            // 1024
#define S_B2  206848            // 1024
#define S_W3  207872            // 1024
#define S_RED 208896            // 4608: sred[128][9]
#define S_ADV 213504            // 512
#define S_POS 214016            // 128
#define S_INV 214144            // 512
#define SM_TOT 214656

__global__ void __launch_bounds__(512,1) kfused(const float* __restrict__ qs,
                  const float* __restrict__ b2, const float* __restrict__ W3,
                  const float* __restrict__ b3, float* __restrict__ out){
  extern __shared__ __align__(16) char sm[];
  uint32_t* sA2h = (uint32_t*)(sm + S_A2H);
  uint32_t* sA2l = (uint32_t*)(sm + S_A2L);
  uint32_t* sBh  = (uint32_t*)(sm + S_BH);
  uint32_t* sBl  = (uint32_t*)(sm + S_BL);
  float*    sD   = (float*)(sm + S_D);
  uint32_t* rqh  = (uint32_t*)(sm + S_RQH);
  uint32_t* rql  = (uint32_t*)(sm + S_RQL);
  float* sW1s = (float*)(sm + S_SW1);
  float* b2s  = (float*)(sm + S_B2);
  float* w3s  = (float*)(sm + S_W3);
  float (*sred)[9] = (float(*)[9])(sm + S_RED);
  float* advs = (float*)(sm + S_ADV);
  unsigned char* poss = (unsigned char*)(sm + S_POS);
  int (*s_inv)[AA] = (int(*)[AA])(sm + S_INV);

  const int tid  = threadIdx.x;
  const int b    = blockIdx.x;
  const int lane = tid & 31;
  const int warp = tid >> 5;
  const int wa   = warp & 7;       // delta phase: agent position a; GEMM2: mblk
  const int nh   = warp >> 3;

  if (tid < 256){
    b2s[tid]  = b2[tid];
    w3s[tid]  = W3[tid];
    sW1s[tid] = g_sW1[b*EM + tid];
  }

  // RNG + permutations
  if (tid < SS){
    int s = tid;
    unsigned base = (unsigned)((b*SS + s)*AA);
    float u[AA];
    #pragma unroll
    for(int a=0;a<AA;a++){
      uint32_t o0, o1;
      threefry2x32(0u, base + a, o0, o1);
      u[a] = bits_to_unit(o0 ^ o1);
    }
    int ord[AA];
    #pragma unroll
    for(int i=0;i<AA;i++) ord[i]=i;
    for(int i=1;i<AA;i++){
      int oi = ord[i]; float ku = u[oi]; int j=i;
      while(j>0 && u[ord[j-1]] > ku){ ord[j]=ord[j-1]; j--; }
      ord[j]=oi;
    }
    #pragma unroll
    for(int r=0;r<AA;r++) s_inv[s][ord[r]] = r;
    #pragma unroll
    for(int i=0;i<AA;i++) poss[s*8 + i] = (unsigned char)ord[i];
  }
  __syncthreads();

  // rq split pairs: rqh/rql[(s*8+a)*8+pr] = bf16x2 split of (q[na=2pr], q[na=2pr+1]) of agent inv[s][a]
  for(int e=tid; e<1024; e+=512){
    int s  = e >> 6;
    int a  = (e >> 3) & 7;
    int pr = e & 7;
    const float* qp = &qs[b*(AA*NACT) + s_inv[s][a]*NACT + pr*2];
    uint32_t h, l;
    split2(qp[0], qp[1], h, l);
    rqh[e] = h;
    rql[e] = l;
  }
  __syncthreads();

  // ---- delta A fragment (per warp, agent position a = wa): A[16 s,16 na] ----
  uint32_t ah[4], al[4];
  {
    int s0 = lane >> 2;
    int pr = lane & 3;
    int e0 = (s0*8 + wa)*8 + pr;
    int e1 = ((s0+8)*8 + wa)*8 + pr;
    ah[0] = rqh[e0];   al[0] = rql[e0];
    ah[1] = rqh[e1];   al[1] = rql[e1];
    ah[2] = rqh[e0+4]; al[2] = rql[e0+4];
    ah[3] = rqh[e1+4]; al[3] = rql[e1+4];
  }

  // stage GEMM2 B chunk 0 (B dbuf unused until GEMM2)
  {
    ((uint4*)sBh)[tid & 511] = ((const uint4*)g_Bh)[tid];
    ((uint4*)sBl)[tid & 511] = ((const uint4*)g_Bl)[tid];
  }

  // ---- delta GEMM: D_a[16 s, 128 n-half] ; 48 MMA/warp, B1 from global (L2) ----
  float d[16][4];
  #pragma unroll
  for(int i=0;i<16;i++){ d[i][0]=0.f; d[i][1]=0.f; d[i][2]=0.f; d[i][3]=0.f; }
  {
    const uint32_t* B1h = g_B1h + ((wa*32 + nh*16)*32)*2;
    const uint32_t* B1l = g_B1l + ((wa*32 + nh*16)*32)*2;
    #pragma unroll
    for(int nb=0; nb<16; nb++){
      uint2 bh = *(const uint2*)&B1h[(nb*32 + lane)*2];
      uint2 bl = *(const uint2*)&B1l[(nb*32 + lane)*2];
      mma16816(d[nb], ah, bh.x, bh.y);
      mma16816(d[nb], al, bh.x, bh.y);
      mma16816(d[nb], ah, bl.x, bl.y);
    }
  }

  // ---- chunked prefix-scan + A2 fragment emit (4 chunks x 64 cols) ----
  for(int ch=0; ch<4; ch++){
    __syncthreads();   // previous chunk's emit done before overwriting sD
    if (nh == (ch>>1)){
      int nb0 = (ch&1)*8;
      int s0  = lane >> 2;
      int cb  = (lane & 3)*2;
      #pragma unroll
      for(int k8=0; k8<8; k8++){
        int nb = nb0 + k8;
        int cl = k8*8 + cb;
        *(float2*)&sD[(s0*8 + wa)*66 + cl]     = make_float2(d[nb][0], d[nb][1]);
        *(float2*)&sD[((s0+8)*8 + wa)*66 + cl] = make_float2(d[nb][2], d[nb][3]);
      }
    }
    __syncthreads();
    if (tid < 128){
      int sgrp = tid >> 4;
      int kk   = (tid >> 2) & 3;
      int kp   = tid & 3;
      int kblk2 = ch*4 + kk;
      int clp  = kk*16 + kp*2;
      int c0g  = kblk2*16 + kp*2;
      int s0 = sgrp*2, s1 = s0 + 1;
      float a0c0 = sW1s[c0g],   a0c1 = sW1s[c0g+1];
      float a0c8 = sW1s[c0g+8], a0c9 = sW1s[c0g+9];
      float acc0[4] = {a0c0, a0c1, a0c8, a0c9};
      float acc1[4] = {a0c0, a0c1, a0c8, a0c9};
      #pragma unroll
      for(int j=0;j<AA;j++){
        float2 p00 = *(const float2*)&sD[(s0*8+j)*66 + clp];
        float2 p08 = *(const float2*)&sD[(s0*8+j)*66 + clp + 8];
        float2 p10 = *(const float2*)&sD[(s1*8+j)*66 + clp];
        float2 p18 = *(const float2*)&sD[(s1*8+j)*66 + clp + 8];
        acc0[0]+=p00.x; acc0[1]+=p00.y; acc0[2]+=p08.x; acc0[3]+=p08.y;
        acc1[0]+=p10.x; acc1[1]+=p10.y; acc1[2]+=p18.x; acc1[3]+=p18.y;
        uint4 hv, lv;
        split2(fmaxf(acc0[0],0.f), fmaxf(acc0[1],0.f), hv.x, lv.x);
        split2(fmaxf(acc1[0],0.f), fmaxf(acc1[1],0.f), hv.y, lv.y);
        split2(fmaxf(acc0[2],0.f), fmaxf(acc0[3],0.f), hv.z, lv.z);
        split2(fmaxf(acc1[2],0.f), fmaxf(acc1[3],0.f), hv.w, lv.w);
        int lane2 = j*4 + kp;
        int o = ((sgrp*16 + kblk2)*32 + lane2)*4;
        *(uint4*)&sA2h[o] = hv;
        *(uint4*)&sA2l[o] = lv;
      }
    }
  }
  __syncthreads();

  // ---- GEMM2: adv = relu(h1 @ W2 + b2) . W3 ; R8-proven loop, A from smem ----
  #pragma unroll
  for(int i=0;i<16;i++){ d[i][0]=0.f; d[i][1]=0.f; d[i][2]=0.f; d[i][3]=0.f; }

  for(int kb=0; kb<16; kb++){
    uint4 ph, pl;
    if (kb < 15){
      ph = ((const uint4*)(g_Bh + (kb+1)*2048))[tid];
      pl = ((const uint4*)(g_Bl + (kb+1)*2048))[tid];
    }
    uint32_t a2h[4], a2l[4];
    {
      int o = ((wa*16 + kb)*32 + lane)*4;
      *(uint4*)a2h = *(const uint4*)&sA2h[o];
      *(uint4*)a2l = *(const uint4*)&sA2l[o];
    }
    const uint32_t* curh = &sBh[(kb&1)*2048];
    const uint32_t* curl = &sBl[(kb&1)*2048];
    #pragma unroll
    for(int nb=0; nb<16; nb++){
      int ng  = nh*16 + nb;
      int off = (ng*32 + lane)*2;
      uint2 bh = *(const uint2*)&curh[off];
      uint2 bl = *(const uint2*)&curl[off];
      mma16816(d[nb], a2h, bh.x, bh.y);
      mma16816(d[nb], a2l, bh.x, bh.y);
      mma16816(d[nb], a2h, bl.x, bl.y);
    }
    if (kb < 15){
      ((uint4*)&sBh[((kb+1)&1)*2048])[tid & 511] = ph;
      ((uint4*)&sBl[((kb+1)&1)*2048])[tid & 511] = pl;
    }
    __syncthreads();
  }

  // ---- epilogue: relu(d + b2) dot W3, quad shfl-reduce, shapley ----
  float p0 = 0.f, p1 = 0.f;
  #pragma unroll
  for(int nb=0; nb<16; nb++){
    int c0 = (nh*16 + nb)*8 + (lane&3)*2;
    float w0 = w3s[c0], w1 = w3s[c0+1];
    float bb0 = b2s[c0], bb1 = b2s[c0+1];
    p0 += fmaxf(d[nb][0]+bb0, 0.f)*w0 + fmaxf(d[nb][1]+bb1, 0.f)*w1;
    p1 += fmaxf(d[nb][2]+bb0, 0.f)*w0 + fmaxf(d[nb][3]+bb1, 0.f)*w1;
  }
  p0 += __shfl_xor_sync(0xFFFFFFFFu, p0, 1);
  p0 += __shfl_xor_sync(0xFFFFFFFFu, p0, 2);
  p1 += __shfl_xor_sync(0xFFFFFFFFu, p1, 1);
  p1 += __shfl_xor_sync(0xFFFFFFFFu, p1, 2);
  if ((lane & 3) == 0){
    int r0 = wa*16 + (lane>>2);
    sred[r0  ][nh] = p0;
    sred[r0+8][nh] = p1;
  }
  __syncthreads();
  if (tid < 128){
    advs[tid] = b3[0] + sred[tid][0] + sred[tid][1];
  }
  __syncthreads();
  if (tid < 8){
    float sum = 0.f;
    #pragma unroll
    for(int s=0;s<SS;s++){
      sum += advs[s*8 + (int)poss[s*8 + tid]];
    }
    out[b*8 + tid] = g_v[b] + sum * (1.0f/16.0f);
  }
}

extern "C" void kernel_launch(void* const* d_in, const int* in_sizes, int n_in,
                              void* d_out, int out_size){
  const float* states   = (const float*)d_in[0];
  const float* agent_qs = (const float*)d_in[1];
  const float* W1  = (const float*)d_in[2];
  const float* b1  = (const float*)d_in[3];
  const float* W2  = (const float*)d_in[4];
  const float* b2  = (const float*)d_in[5];
  const float* W3  = (const float*)d_in[6];
  const float* b3  = (const float*)d_in[7];
  const float* Vw1 = (const float*)d_in[8];
  const float* Vb1 = (const float*)d_in[9];
  const float* Vw2 = (const float*)d_in[10];
  const float* Vb2 = (const float*)d_in[11];
  float* out = (float*)d_out;

  cudaFuncSetAttribute(kfused, cudaFuncAttributeMaxDynamicSharedMemorySize, SM_TOT);

  k0_prepW2  <<<128, 256>>>(W2);
  k0b_prepW1x<<<64, 256>>>(W1);
  k1_state   <<<NB/4, 256>>>(states, W1, b1, Vw1, Vb1, Vw2, Vb2);
  kfused     <<<NB, 512, SM_TOT>>>(agent_qs, b2, W3, b3, out);
}

// round 17
// speedup vs baseline: 2.1811x; 2.1811x over previous
#include <cuda_runtime.h>
#include <cuda_bf16.h>
#include <stdint.h>

typedef unsigned long long ull;

#define NB   1024
#define SS   16
#define AA   8
#define NACT 16
#define SD   256
#define EM   256

// ---------------- device scratch ----------------
__device__ float g_sW1[NB*EM];
__device__ float g_v[NB];
// GEMM2 B (W2^T) fragments: [kblk(16)][nblk(32)][lane(32)][reg(2)] u32, split hi/lo
__device__ uint32_t g_Bh[16*32*32*2];
__device__ uint32_t g_Bl[16*32*32*2];
// GEMM1 B (W1x) fragments: [kblk(8)=agent pos][nblk(32)][lane(32)][reg(2)] u32, split hi/lo
__device__ uint32_t g_B1h[8*32*32*2];
__device__ uint32_t g_B1l[8*32*32*2];

// ---------------- threefry2x32 (JAX exact, key(42)) ----------------
__device__ __forceinline__ uint32_t rotl(uint32_t x, int r){ return (x<<r)|(x>>(32-r)); }
__device__ __forceinline__ void threefry2x32(uint32_t c0, uint32_t c1, uint32_t &o0, uint32_t &o1){
  const uint32_t k0 = 0u, k1v = 42u, k2 = 0u ^ 42u ^ 0x1BD11BDAu;
  uint32_t x0 = c0 + k0;
  uint32_t x1 = c1 + k1v;
#define TF_R(rot) { x0 += x1; x1 = rotl(x1, rot); x1 ^= x0; }
  TF_R(13) TF_R(15) TF_R(26) TF_R(6)
  x0 += k1v; x1 += k2 + 1u;
  TF_R(17) TF_R(29) TF_R(16) TF_R(24)
  x0 += k2;  x1 += k0 + 2u;
  TF_R(13) TF_R(15) TF_R(26) TF_R(6)
  x0 += k0;  x1 += k1v + 3u;
  TF_R(17) TF_R(29) TF_R(16) TF_R(24)
  x0 += k1v; x1 += k2 + 4u;
  TF_R(13) TF_R(15) TF_R(26) TF_R(6)
  x0 += k2;  x1 += k0 + 5u;
#undef TF_R
  o0 = x0; o1 = x1;
}
__device__ __forceinline__ float bits_to_unit(uint32_t bits){
  return __uint_as_float(0x3f800000u | (bits >> 9)) - 1.0f;
}

// ---------------- packed helpers ----------------
__device__ __forceinline__ uint32_t pack_bf16x2(float v0, float v1){
  uint32_t r;
  asm("cvt.rn.bf16x2.f32 %0, %1, %2;" : "=r"(r) : "f"(v1), "f"(v0));
  return r;
}
__device__ __forceinline__ void split2(float v0, float v1, uint32_t &h, uint32_t &l){
  h = pack_bf16x2(v0, v1);
  float h0 = __uint_as_float(h << 16);
  float h1 = __uint_as_float(h & 0xFFFF0000u);
  l = pack_bf16x2(v0 - h0, v1 - h1);
}
__device__ __forceinline__ void split_bf16(float v, uint32_t &h, uint32_t &l){
  __nv_bfloat16 hb = __float2bfloat16(v);
  float lf = v - __bfloat162float(hb);
  __nv_bfloat16 lb = __float2bfloat16(lf);
  h = (uint32_t)__bfloat16_as_ushort(hb);
  l = (uint32_t)__bfloat16_as_ushort(lb);
}

__device__ __forceinline__ void mma16816(float* d, const uint32_t* a, uint32_t b0, uint32_t b1){
  asm volatile("mma.sync.aligned.m16n8k16.row.col.f32.bf16.bf16.f32 "
    "{%0,%1,%2,%3}, {%4,%5,%6,%7}, {%8,%9}, {%0,%1,%2,%3};"
    : "+f"(d[0]),"+f"(d[1]),"+f"(d[2]),"+f"(d[3])
    : "r"(a[0]),"r"(a[1]),"r"(a[2]),"r"(a[3]), "r"(b0),"r"(b1));
}

// ============ K0: W2 -> GEMM2 B fragments ============
__global__ void k0_prepW2(const float* __restrict__ W2){
  int idx = blockIdx.x*256 + threadIdx.x;   // 32768
  int kp = idx >> 8, n = idx & 255;
  int k = kp*2;
  float v0 = W2[k*EM + n];
  float v1 = W2[(k+1)*EM + n];
  uint32_t h0,l0,h1,l1;
  split_bf16(v0,h0,l0); split_bf16(v1,h1,l1);
  uint32_t hi = h0 | (h1<<16);
  uint32_t lo = l0 | (l1<<16);
  int kblk = kp>>3;
  int reg  = (kp>>2)&1;
  int lane = (n&7)*4 + (kp&3);
  int nblk = n>>3;
  int bidx = ((kblk*32+nblk)*32+lane)*2 + reg;
  g_Bh[bidx] = hi;
  g_Bl[bidx] = lo;
}

// ============ K0b: W1x (rows SD..SD+127) -> GEMM1 B fragments ============
__global__ void k0b_prepW1x(const float* __restrict__ W1){
  int idx = blockIdx.x*256 + threadIdx.x;   // 16384
  int kp = idx >> 8, n = idx & 255;
  int k = kp*2;
  float v0 = W1[(SD + k)*EM + n];
  float v1 = W1[(SD + k + 1)*EM + n];
  uint32_t h0,l0,h1,l1;
  split_bf16(v0,h0,l0); split_bf16(v1,h1,l1);
  uint32_t hi = h0 | (h1<<16);
  uint32_t lo = l0 | (l1<<16);
  int kblk = kp>>3;          // 0..7 = agent position a
  int reg  = (kp>>2)&1;
  int lane = (n&7)*4 + (kp&3);
  int nblk = n>>3;
  int bidx = ((kblk*32+nblk)*32+lane)*2 + reg;
  g_B1h[bidx] = hi;
  g_B1l[bidx] = lo;
}

// ============ K1: per-b state terms, 4 b per CTA ============
__global__ void __launch_bounds__(256) k1_state(const float* __restrict__ st,
                         const float* __restrict__ W1,
                         const float* __restrict__ b1, const float* __restrict__ Vw1,
                         const float* __restrict__ Vb1, const float* __restrict__ Vw2,
                         const float* __restrict__ Vb2){
  const int b0 = blockIdx.x * 4;
  const int n  = threadIdx.x;
  __shared__ float s_st[4][SD];
  __shared__ float red[4][EM];
  #pragma unroll
  for(int bi=0;bi<4;bi++) s_st[bi][n] = st[(b0+bi)*SD + n];
  __syncthreads();
  float acc[4], accv[4];
  float bb1 = b1[n], vbb = Vb1[n];
  #pragma unroll
  for(int bi=0;bi<4;bi++){ acc[bi]=bb1; accv[bi]=vbb; }
  #pragma unroll 4
  for(int k=0;k<SD;k++){
    float w  = W1 [k*EM + n];
    float vw = Vw1[k*EM + n];
    #pragma unroll
    for(int bi=0;bi<4;bi++){
      float sv = s_st[bi][k];
      acc[bi]  = fmaf(sv, w,  acc[bi]);
      accv[bi] = fmaf(sv, vw, accv[bi]);
    }
  }
  float vw2 = Vw2[n];
  #pragma unroll
  for(int bi=0;bi<4;bi++){
    g_sW1[(b0+bi)*EM + n] = acc[bi];
    red[bi][n] = fmaxf(accv[bi], 0.f) * vw2;
  }
  __syncthreads();
  int w = n >> 5, l = n & 31;
  if (w < 4){
    float s = 0.f;
    #pragma unroll
    for(int t=0;t<8;t++) s += red[w][l + t*32];
    #pragma unroll
    for(int off=16; off>0; off>>=1) s += __shfl_xor_sync(0xFFFFFFFFu, s, off);
    if (l == 0) g_v[b0 + w] = s + Vb2[0];
  }
}

// ============ Fused: RNG + chunked delta-MMA/prefix-scan + GEMM2 + shapley ============
// smem layout (bytes)
#define S_A2H 0                 // 65536: GEMM2 A hi frags [mblk*16+kblk][lane][4]
#define S_A2L 65536             // 65536: GEMM2 A lo frags
#define S_BH  131072            // 16384: GEMM2 B hi dbuf [buf][2048 u32]
#define S_BL  147456            // 16384: GEMM2 B lo dbuf
#define S_D   163840            // 33792: delta chunk [s*8+a][66 floats]
#define S_RQH 197632            // 4096: rq hi pairs [s(16)][a(8)][pr(8)]
#define S_RQL 201728            // 4096
#define S_SW1 205824            // 1024
#define S_B2  206848            // 1024
#define S_W3  207872            // 1024
#define S_RED 208896            // 4608: sred[128][9]
#define S_ADV 213504            // 512
#define S_POS 214016            // 128
#define S_INV 214144            // 512
#define SM_TOT 214656

__global__ void __launch_bounds__(512,1) kfused(const float* __restrict__ qs,
                  const float* __restrict__ b2, const float* __restrict__ W3,
                  const float* __restrict__ b3, float* __restrict__ out){
  extern __shared__ __align__(16) char sm[];
  uint32_t* sA2h = (uint32_t*)(sm + S_A2H);
  uint32_t* sA2l = (uint32_t*)(sm + S_A2L);
  uint32_t* sBh  = (uint32_t*)(sm + S_BH);
  uint32_t* sBl  = (uint32_t*)(sm + S_BL);
  float*    sD   = (float*)(sm + S_D);
  uint32_t* rqh  = (uint32_t*)(sm + S_RQH);
  uint32_t* rql  = (uint32_t*)(sm + S_RQL);
  float* sW1s = (float*)(sm + S_SW1);
  float* b2s  = (float*)(sm + S_B2);
  float* w3s  = (float*)(sm + S_W3);
  float (*sred)[9] = (float(*)[9])(sm + S_RED);
  float* advs = (float*)(sm + S_ADV);
  unsigned char* poss = (unsigned char*)(sm + S_POS);
  int (*s_inv)[AA] = (int(*)[AA])(sm + S_INV);

  const int tid  = threadIdx.x;
  const int b    = blockIdx.x;
  const int lane = tid & 31;
  const int warp = tid >> 5;
  const int wa   = warp & 7;       // delta phase: agent position a; GEMM2: mblk
  const int nh   = warp >> 3;

  if (tid < 256){
    b2s[tid]  = b2[tid];
    w3s[tid]  = W3[tid];
    sW1s[tid] = g_sW1[b*EM + tid];
  }

  // RNG + permutations
  if (tid < SS){
    int s = tid;
    unsigned base = (unsigned)((b*SS + s)*AA);
    float u[AA];
    #pragma unroll
    for(int a=0;a<AA;a++){
      uint32_t o0, o1;
      threefry2x32(0u, base + a, o0, o1);
      u[a] = bits_to_unit(o0 ^ o1);
    }
    int ord[AA];
    #pragma unroll
    for(int i=0;i<AA;i++) ord[i]=i;
    for(int i=1;i<AA;i++){
      int oi = ord[i]; float ku = u[oi]; int j=i;
      while(j>0 && u[ord[j-1]] > ku){ ord[j]=ord[j-1]; j--; }
      ord[j]=oi;
    }
    #pragma unroll
    for(int r=0;r<AA;r++) s_inv[s][ord[r]] = r;
    #pragma unroll
    for(int i=0;i<AA;i++) poss[s*8 + i] = (unsigned char)ord[i];
  }
  __syncthreads();

  // rq split pairs: rqh/rql[(s*8+a)*8+pr] = bf16x2 split of (q[na=2pr], q[na=2pr+1]) of agent inv[s][a]
  for(int e=tid; e<1024; e+=512){
    int s  = e >> 6;
    int a  = (e >> 3) & 7;
    int pr = e & 7;
    const float* qp = &qs[b*(AA*NACT) + s_inv[s][a]*NACT + pr*2];
    uint32_t h, l;
    split2(qp[0], qp[1], h, l);
    rqh[e] = h;
    rql[e] = l;
  }
  __syncthreads();

  // ---- delta A fragment (per warp, agent position a = wa): A[16 s,16 na] ----
  uint32_t ah[4], al[4];
  {
    int s0 = lane >> 2;
    int pr = lane & 3;
    int e0 = (s0*8 + wa)*8 + pr;
    int e1 = ((s0+8)*8 + wa)*8 + pr;
    ah[0] = rqh[e0];   al[0] = rql[e0];
    ah[1] = rqh[e1];   al[1] = rql[e1];
    ah[2] = rqh[e0+4]; al[2] = rql[e0+4];
    ah[3] = rqh[e1+4]; al[3] = rql[e1+4];
  }

  // stage GEMM2 B chunk 0 (B dbuf unused until GEMM2)
  {
    ((uint4*)sBh)[tid & 511] = ((const uint4*)g_Bh)[tid];
    ((uint4*)sBl)[tid & 511] = ((const uint4*)g_Bl)[tid];
  }

  // ---- chunked: delta-MMA (12 MMAs/warp) -> sD -> prefix-scan emit, per 64-col chunk ----
  for(int ch=0; ch<4; ch++){
    // compute this chunk's deltas: warp (wa, nh) covers ng = ch*8 + nh*4 + {0..3}
    float dd[4][4];
    #pragma unroll
    for(int i=0;i<4;i++){ dd[i][0]=0.f; dd[i][1]=0.f; dd[i][2]=0.f; dd[i][3]=0.f; }
    {
      int ng0 = ch*8 + nh*4;
      const uint32_t* B1h = g_B1h + ((wa*32 + ng0)*32)*2;
      const uint32_t* B1l = g_B1l + ((wa*32 + ng0)*32)*2;
      #pragma unroll
      for(int i=0;i<4;i++){
        uint2 bh = *(const uint2*)&B1h[(i*32 + lane)*2];
        uint2 bl = *(const uint2*)&B1l[(i*32 + lane)*2];
        mma16816(dd[i], ah, bh.x, bh.y);
        mma16816(dd[i], al, bh.x, bh.y);
        mma16816(dd[i], ah, bl.x, bl.y);
      }
    }
    __syncthreads();   // previous chunk's scan finished reading sD
    // store deltas: local col cl = (nh*4+i)*8 + (lane&3)*2 within chunk
    {
      int s0 = lane >> 2;
      int cb = (lane & 3)*2;
      #pragma unroll
      for(int i=0;i<4;i++){
        int cl = (nh*4 + i)*8 + cb;
        *(float2*)&sD[(s0*8 + wa)*66 + cl]     = make_float2(dd[i][0], dd[i][1]);
        *(float2*)&sD[((s0+8)*8 + wa)*66 + cl] = make_float2(dd[i][2], dd[i][3]);
      }
    }
    __syncthreads();
    // prefix-scan + A2 emit (128 threads; 2 samples per thread)
    if (tid < 128){
      int sgrp = tid >> 4;
      int kk   = (tid >> 2) & 3;
      int kp   = tid & 3;
      int kblk2 = ch*4 + kk;
      int clp  = kk*16 + kp*2;
      int c0g  = kblk2*16 + kp*2;
      int s0 = sgrp*2, s1 = s0 + 1;
      float a0c0 = sW1s[c0g],   a0c1 = sW1s[c0g+1];
      float a0c8 = sW1s[c0g+8], a0c9 = sW1s[c0g+9];
      float acc0[4] = {a0c0, a0c1, a0c8, a0c9};
      float acc1[4] = {a0c0, a0c1, a0c8, a0c9};
      #pragma unroll
      for(int j=0;j<AA;j++){
        float2 p00 = *(const float2*)&sD[(s0*8+j)*66 + clp];
        float2 p08 = *(const float2*)&sD[(s0*8+j)*66 + clp + 8];
        float2 p10 = *(const float2*)&sD[(s1*8+j)*66 + clp];
        float2 p18 = *(const float2*)&sD[(s1*8+j)*66 + clp + 8];
        acc0[0]+=p00.x; acc0[1]+=p00.y; acc0[2]+=p08.x; acc0[3]+=p08.y;
        acc1[0]+=p10.x; acc1[1]+=p10.y; acc1[2]+=p18.x; acc1[3]+=p18.y;
        uint4 hv, lv;
        split2(fmaxf(acc0[0],0.f), fmaxf(acc0[1],0.f), hv.x, lv.x);
        split2(fmaxf(acc1[0],0.f), fmaxf(acc1[1],0.f), hv.y, lv.y);
        split2(fmaxf(acc0[2],0.f), fmaxf(acc0[3],0.f), hv.z, lv.z);
        split2(fmaxf(acc1[2],0.f), fmaxf(acc1[3],0.f), hv.w, lv.w);
        int lane2 = j*4 + kp;
        int o = ((sgrp*16 + kblk2)*32 + lane2)*4;
        *(uint4*)&sA2h[o] = hv;
        *(uint4*)&sA2l[o] = lv;
      }
    }
  }
  __syncthreads();

  // ---- GEMM2: adv = relu(h1 @ W2 + b2) . W3 ; R8-proven loop, A from smem ----
  float d[16][4];
  #pragma unroll
  for(int i=0;i<16;i++){ d[i][0]=0.f; d[i][1]=0.f; d[i][2]=0.f; d[i][3]=0.f; }

  for(int kb=0; kb<16; kb++){
    uint4 ph, pl;
    if (kb < 15){
      ph = ((const uint4*)(g_Bh + (kb+1)*2048))[tid];
      pl = ((const uint4*)(g_Bl + (kb+1)*2048))[tid];
    }
    uint32_t a2h[4], a2l[4];
    {
      int o = ((wa*16 + kb)*32 + lane)*4;
      *(uint4*)a2h = *(const uint4*)&sA2h[o];
      *(uint4*)a2l = *(const uint4*)&sA2l[o];
    }
    const uint32_t* curh = &sBh[(kb&1)*2048];
    const uint32_t* curl = &sBl[(kb&1)*2048];
    #pragma unroll
    for(int nb=0; nb<16; nb++){
      int ng  = nh*16 + nb;
      int off = (ng*32 + lane)*2;
      uint2 bh = *(const uint2*)&curh[off];
      uint2 bl = *(const uint2*)&curl[off];
      mma16816(d[nb], a2h, bh.x, bh.y);
      mma16816(d[nb], a2l, bh.x, bh.y);
      mma16816(d[nb], a2h, bl.x, bl.y);
    }
    if (kb < 15){
      ((uint4*)&sBh[((kb+1)&1)*2048])[tid & 511] = ph;
      ((uint4*)&sBl[((kb+1)&1)*2048])[tid & 511] = pl;
    }
    __syncthreads();
  }

  // ---- epilogue: relu(d + b2) dot W3, quad shfl-reduce, shapley ----
  float p0 = 0.f, p1 = 0.f;
  #pragma unroll
  for(int nb=0; nb<16; nb++){
    int c0 = (nh*16 + nb)*8 + (lane&3)*2;
    float w0 = w3s[c0], w1 = w3s[c0+1];
    float bb0 = b2s[c0], bb1 = b2s[c0+1];
    p0 += fmaxf(d[nb][0]+bb0, 0.f)*w0 + fmaxf(d[nb][1]+bb1, 0.f)*w1;
    p1 += fmaxf(d[nb][2]+bb0, 0.f)*w0 + fmaxf(d[nb][3]+bb1, 0.f)*w1;
  }
  p0 += __shfl_xor_sync(0xFFFFFFFFu, p0, 1);
  p0 += __shfl_xor_sync(0xFFFFFFFFu, p0, 2);
  p1 += __shfl_xor_sync(0xFFFFFFFFu, p1, 1);
  p1 += __shfl_xor_sync(0xFFFFFFFFu, p1, 2);
  if ((lane & 3) == 0){
    int r0 = wa*16 + (lane>>2);
    sred[r0  ][nh] = p0;
    sred[r0+8][nh] = p1;
  }
  __syncthreads();
  if (tid < 128){
    advs[tid] = b3[0] + sred[tid][0] + sred[tid][1];
  }
  __syncthreads();
  if (tid < 8){
    float sum = 0.f;
    #pragma unroll
    for(int s=0;s<SS;s++){
      sum += advs[s*8 + (int)poss[s*8 + tid]];
    }
    out[b*8 + tid] = g_v[b] + sum * (1.0f/16.0f);
  }
}

extern "C" void kernel_launch(void* const* d_in, const int* in_sizes, int n_in,
                              void* d_out, int out_size){
  const float* states   = (const float*)d_in[0];
  const float* agent_qs = (const float*)d_in[1];
  const float* W1  = (const float*)d_in[2];
  const float* b1  = (const float*)d_in[3];
  const float* W2  = (const float*)d_in[4];
  const float* b2  = (const float*)d_in[5];
  const float* W3  = (const float*)d_in[6];
  const float* b3  = (const float*)d_in[7];
  const float* Vw1 = (const float*)d_in[8];
  const float* Vb1 = (const float*)d_in[9];
  const float* Vw2 = (const float*)d_in[10];
  const float* Vb2 = (const float*)d_in[11];
  float* out = (float*)d_out;

  cudaFuncSetAttribute(kfused, cudaFuncAttributeMaxDynamicSharedMemorySize, SM_TOT);

  k0_prepW2  <<<128, 256>>>(W2);
  k0b_prepW1x<<<64, 256>>>(W1);
  k1_state   <<<NB/4, 256>>>(states, W1, b1, Vw1, Vb1, Vw2, Vb2);
  kfused     <<<NB, 512, SM_TOT>>>(agent_qs, b2, W3, b3, out);
}